// round 15
// baseline (speedup 1.0000x reference)
#include <cuda_runtime.h>
#include <cuda_fp16.h>
#include <cstdint>

// SingleSelfHeadAttention b=4, s=2048, d=1024, causal, fp32 I/O.
// R15: fp16 score matrix; one-load uint4 softmax; compacted triangular
//      scores grid. GEMMs at the SMEM-crossbar wall (68% tensor) unchanged.

static constexpr int Bn = 4;
static constexpr int Sq = 2048;
static constexpr int Dd = 1024;
static constexpr int Mm = Bn * Sq;          // 8192

// ---------------- device scratch ----------------
__device__ __half g_xr [(size_t)Mm * Dd];
__device__ __half g_wqt[(size_t)Dd * Dd], g_wkt[(size_t)Dd * Dd];
__device__ __half g_wvt[(size_t)Dd * Dd], g_wot[(size_t)Dd * Dd];
__device__ __half g_qh[(size_t)Mm * Dd];
__device__ __half g_kh[(size_t)Mm * Dd];
__device__ __half g_vh[(size_t)Mm * Dd];
__device__ __half g_vwot[(size_t)Bn * Dd * Sq];   // (V·Wo)^T per batch [d'][s]
__device__ __half g_Sh[(size_t)Bn * Sq * Sq];     // fp16 scores
__device__ __half g_ph[(size_t)Bn * Sq * Sq];     // fp16 probs

// ---------------- PTX helpers ----------------
__device__ __forceinline__ uint32_t smem_u32(const void* p) {
    uint32_t a;
    asm("{ .reg .u64 t; cvta.to.shared.u64 t, %1; cvt.u32.u64 %0, t; }" : "=r"(a) : "l"(p));
    return a;
}
#define CP_ASYNC16(dst, src) \
    asm volatile("cp.async.cg.shared.global [%0], [%1], 16;" :: "r"(dst), "l"(src))
#define CP_COMMIT() asm volatile("cp.async.commit_group;" ::: "memory")
#define CP_WAIT1()  asm volatile("cp.async.wait_group 1;" ::: "memory")

__device__ __forceinline__ void ldsm_x4(uint32_t* r, uint32_t addr) {
    asm volatile("ldmatrix.sync.aligned.m8n8.x4.shared.b16 {%0,%1,%2,%3}, [%4];"
        : "=r"(r[0]), "=r"(r[1]), "=r"(r[2]), "=r"(r[3]) : "r"(addr));
}
__device__ __forceinline__ void mma_f16(float* c, const uint32_t* a, const uint32_t* b) {
    asm volatile("mma.sync.aligned.m16n8k16.row.col.f32.f16.f16.f32 "
        "{%0,%1,%2,%3}, {%4,%5,%6,%7}, {%8,%9}, {%0,%1,%2,%3};"
        : "+f"(c[0]), "+f"(c[1]), "+f"(c[2]), "+f"(c[3])
        : "r"(a[0]), "r"(a[1]), "r"(a[2]), "r"(a[3]), "r"(b[0]), "r"(b[1]));
}
__device__ __forceinline__ uint32_t swz(uint32_t off) {   // 128B-row XOR swizzle
    return off ^ ((off >> 3) & 0x70);
}

// ---------------- GEMM config: 128x128 tile, 128 threads ----------------
#define TM_CTA 128
#define TN_CTA 128
#define NTHR   128
#define A_TILE (TM_CTA * 128)            // 16384 B
#define STAGE  (2 * A_TILE)              // 32768
#define NSTAGE 3
#define GEMM_SMEM (NSTAGE * STAGE)       // 98304 -> 2 CTAs/SM

__device__ __forceinline__ void load_T_async(uint32_t dst, const __half* src,
                                             int ldK, int tid) {
    #pragma unroll
    for (int j = 0; j < 8; j++) {
        int s = tid + j * NTHR;
        int r = s >> 3, c = s & 7;
        CP_ASYNC16(dst + swz(r * 128 + c * 16), src + (size_t)r * ldK + c * 8);
    }
}

// Shared single-barrier multistage mainloop. acc[4][8][4] += A·B^T over nchunk*64 K.
__device__ __forceinline__ void mainloop(const __half* __restrict__ pA,
                                         const __half* __restrict__ pB,
                                         int ldA, int ldB, int nchunk,
                                         uint32_t sb, int tid, int lane,
                                         int wm, int wn, float acc[4][8][4])
{
    #pragma unroll
    for (int p = 0; p < 2; p++) {
        if (p < nchunk) {
            uint32_t st = sb + p * STAGE;
            load_T_async(st, pA + ((size_t)p << 6), ldA, tid);
            load_T_async(st + A_TILE, pB + ((size_t)p << 6), ldB, tid);
        }
        CP_COMMIT();
    }

    const uint32_t arow = (lane & 7) + ((lane & 8)  ? 8 : 0);
    const uint32_t acol = (lane & 16) ? 16u : 0u;
    const uint32_t brow = (lane & 7) + ((lane & 16) ? 8 : 0);
    const uint32_t bcol = (lane & 8)  ? 16u : 0u;

    for (int c = 0; c < nchunk; ++c) {
        CP_WAIT1();
        __syncthreads();

        if (c + 2 < nchunk) {
            uint32_t st = sb + ((c + 2) % NSTAGE) * STAGE;
            load_T_async(st, pA + ((size_t)(c + 2) << 6), ldA, tid);
            load_T_async(st + A_TILE, pB + ((size_t)(c + 2) << 6), ldB, tid);
        }
        CP_COMMIT();

        const uint32_t base = sb + (c % NSTAGE) * STAGE;
        #pragma unroll
        for (int ks = 0; ks < 4; ks++) {
            const uint32_t kb = ks * 32;
            uint32_t ah[4][4];
            #pragma unroll
            for (int i = 0; i < 4; i++) {
                uint32_t off = swz((wm * 64 + i * 16 + arow) * 128 + kb + acol);
                ldsm_x4(ah[i], base + off);
            }
            #pragma unroll
            for (int j2 = 0; j2 < 4; j2++) {
                uint32_t off = swz((wn * 64 + j2 * 16 + brow) * 128 + kb + bcol);
                uint32_t th[4];
                ldsm_x4(th, base + A_TILE + off);
                const int j0 = j2 * 2, j1 = j2 * 2 + 1;
                #pragma unroll
                for (int i = 0; i < 4; i++) {
                    mma_f16(acc[i][j0], ah[i], &th[0]);
                    mma_f16(acc[i][j1], ah[i], &th[2]);
                }
            }
        }
    }
}

// ---------------- prep: weight transposes (z<4) + x rounding (z==4) --------
__global__ void prep_kernel(const float* __restrict__ x, __half* __restrict__ xr,
                            const float* __restrict__ W0, __half* __restrict__ T0,
                            const float* __restrict__ W1, __half* __restrict__ T1,
                            const float* __restrict__ W2, __half* __restrict__ T2,
                            const float* __restrict__ W3, __half* __restrict__ T3) {
    if (blockIdx.z == 4) {
        size_t i = ((size_t)(blockIdx.y * gridDim.x + blockIdx.x) * 256
                   + threadIdx.y * 32 + threadIdx.x);
        size_t stride = (size_t)gridDim.x * gridDim.y * 256;
        const size_t n = (size_t)Mm * Dd;
        for (; i < n; i += stride) xr[i] = __float2half_rn(x[i]);
        return;
    }
    const float* W = (blockIdx.z == 0) ? W0 : (blockIdx.z == 1) ? W1
                   : (blockIdx.z == 2) ? W2 : W3;
    __half* T = (blockIdx.z == 0) ? T0 : (blockIdx.z == 1) ? T1
              : (blockIdx.z == 2) ? T2 : T3;
    __shared__ float tile[32][33];
    int bx = blockIdx.x * 32, by = blockIdx.y * 32;
    int tx = threadIdx.x, ty = threadIdx.y;
    #pragma unroll
    for (int j = 0; j < 4; j++)
        tile[ty + 8 * j][tx] = W[(size_t)(by + ty + 8 * j) * Dd + bx + tx];
    __syncthreads();
    #pragma unroll
    for (int j = 0; j < 4; j++) {
        float v = tile[tx][ty + 8 * j];
        size_t o = (size_t)(bx + ty + 8 * j) * Dd + by + tx;
        T[o] = __float2half_rn(v);
    }
}

// One-load causal softmax on fp16 scores: thread tid owns cols [8tid, 8tid+8).
__global__ __launch_bounds__(256)
void softmax_causal(const __half* __restrict__ Sh, __half* __restrict__ ph) {
    const int gq = blockIdx.x;
    const int q  = gq & (Sq - 1);
    const uint4* row = (const uint4*)(Sh + (size_t)gq * Sq);   // 256 x 16B
    uint4* out = (uint4*)(ph + (size_t)gq * Sq);
    const int len  = q + 1;
    const int jend = ((q >> 7) + 1) << 7;
    const int tid  = threadIdx.x;
    const int lane = tid & 31;
    const int wrp  = tid >> 5;
    const int col0 = tid << 3;
    __shared__ float redm[8], reds[8];

    float v[8];
    float m = -1e30f;
    if (col0 < len) {
        uint4 t = row[tid];
        const __half2* h2 = (const __half2*)&t;
        #pragma unroll
        for (int k = 0; k < 4; k++) {
            float2 f = __half22float2(h2[k]);
            v[2 * k] = f.x; v[2 * k + 1] = f.y;
        }
        #pragma unroll
        for (int k = 0; k < 8; k++)
            if (col0 + k < len) m = fmaxf(m, v[k]);
    }
    #pragma unroll
    for (int o = 16; o > 0; o >>= 1)
        m = fmaxf(m, __shfl_xor_sync(0xffffffffu, m, o));
    if (lane == 0) redm[wrp] = m;
    __syncthreads();
    if (wrp == 0) {
        float t = (lane < 8) ? redm[lane] : -1e30f;
        #pragma unroll
        for (int o = 4; o > 0; o >>= 1)
            t = fmaxf(t, __shfl_xor_sync(0xffffffffu, t, o));
        if (lane == 0) redm[0] = t;
    }
    __syncthreads();
    m = redm[0];

    float sum = 0.f;
    if (col0 < len) {
        #pragma unroll
        for (int k = 0; k < 8; k++) {
            float e = (col0 + k < len) ? __expf(v[k] - m) : 0.f;
            v[k] = e; sum += e;
        }
    }
    #pragma unroll
    for (int o = 16; o > 0; o >>= 1)
        sum += __shfl_xor_sync(0xffffffffu, sum, o);
    if (lane == 0) reds[wrp] = sum;
    __syncthreads();
    if (wrp == 0) {
        float t = (lane < 8) ? reds[lane] : 0.f;
        #pragma unroll
        for (int o = 4; o > 0; o >>= 1)
            t += __shfl_xor_sync(0xffffffffu, t, o);
        if (lane == 0) reds[0] = t;
    }
    __syncthreads();
    const float inv = 1.0f / reds[0];

    if (col0 < jend) {
        uint4 o4;
        __half2* h2 = (__half2*)&o4;
        const bool full = (col0 < len);
        #pragma unroll
        for (int k = 0; k < 4; k++) {
            float a = full ? v[2 * k] * inv : 0.f;
            float b = full ? v[2 * k + 1] * inv : 0.f;
            h2[k] = __halves2half2(__float2half_rn(a), __float2half_rn(b));
        }
        out[tid] = o4;
    }
}

// ================= QKV combined single-pass GEMM =================
__global__ __launch_bounds__(NTHR, 2)
void gemm_qkv(const __half* __restrict__ xr,
              const __half* __restrict__ wq, const __half* __restrict__ wk,
              const __half* __restrict__ wv,
              const float* __restrict__ bq, const float* __restrict__ bk,
              const float* __restrict__ bv,
              __half* __restrict__ qh, __half* __restrict__ kh,
              __half* __restrict__ vh)
{
    const int bxx = blockIdx.x & 7;
    const int wsel = blockIdx.x >> 3;
    const int by = blockIdx.y;
    const __half* Bw  = (wsel == 0) ? wq : (wsel == 1) ? wk : wv;
    const float* bias = (wsel == 0) ? bq : (wsel == 1) ? bk : bv;
    __half* outp      = (wsel == 0) ? qh : (wsel == 1) ? kh : vh;

    extern __shared__ __align__(16) char smem[];
    const uint32_t sb = smem_u32(smem);
    const int tid  = threadIdx.x;
    const int lane = tid & 31;
    const int wid  = tid >> 5;
    const int wm   = wid >> 1;
    const int wn   = wid & 1;

    float acc[4][8][4] = {};
    mainloop(xr + (size_t)by * TM_CTA * Dd, Bw + (size_t)bxx * TN_CTA * Dd,
             Dd, Dd, Dd >> 6, sb, tid, lane, wm, wn, acc);

    const int m_base = by * TM_CTA + wm * 64;
    const int n_base = bxx * TN_CTA + wn * 64;
    const int rr = lane >> 2;
    const int cc = 2 * (lane & 3);

    #pragma unroll
    for (int j = 0; j < 8; j++) {
        const int col = n_base + j * 8 + cc;
        const float b0 = __ldg(&bias[col]);
        const float b1 = __ldg(&bias[col + 1]);
        #pragma unroll
        for (int i = 0; i < 4; i++) {
            #pragma unroll
            for (int h = 0; h < 2; h++) {
                const int row = m_base + i * 16 + rr + h * 8;
                float v0 = acc[i][j][2 * h + 0] + b0;
                float v1 = acc[i][j][2 * h + 1] + b1;
                size_t o = (size_t)row * Dd + col;
                *(__half2*)(outp + o) =
                    __halves2half2(__float2half_rn(v0), __float2half_rn(v1));
            }
        }
    }
}

// ================= merged scores + (V·Wo)^T GEMM, compact grid =================
// grid.x = 264: t<136 -> triangular score tile (by,bx); t>=136 -> vwo tile.
__global__ __launch_bounds__(NTHR, 2)
void gemm_scvw(const __half* __restrict__ qh, const __half* __restrict__ kh,
               const __half* __restrict__ wot, const __half* __restrict__ vh,
               __half* __restrict__ Sh, __half* __restrict__ vwot, float scale)
{
    const int t = blockIdx.x;
    const int z = blockIdx.z;
    const bool is_sc = (t < 136);
    int by, bx;
    if (is_sc) {
        by = (int)((sqrtf(8.f * t + 1.f) - 1.f) * 0.5f);
        while ((by + 1) * (by + 2) / 2 <= t) by++;
        while (by * (by + 1) / 2 > t) by--;
        bx = t - by * (by + 1) / 2;               // bx <= by (causal)
    } else {
        const int t2 = t - 136;                   // 0..127
        by = t2 >> 4;                             // 0..7  (wot row tile)
        bx = t2 & 15;                             // 0..15 (seq col tile)
    }

    extern __shared__ __align__(16) char smem[];
    const uint32_t sb = smem_u32(smem);
    const int tid  = threadIdx.x;
    const int lane = tid & 31;
    const int wid  = tid >> 5;
    const int wm   = wid >> 1;
    const int wn   = wid & 1;

    const __half* pA;
    const __half* pB;
    if (is_sc) {
        pA = qh + (size_t)z * Sq * Dd + (size_t)by * TM_CTA * Dd;
        pB = kh + (size_t)z * Sq * Dd + (size_t)bx * TN_CTA * Dd;
    } else {
        pA = wot + (size_t)by * TM_CTA * Dd;
        pB = vh + (size_t)z * Sq * Dd + (size_t)bx * TN_CTA * Dd;
    }

    float acc[4][8][4] = {};
    mainloop(pA, pB, Dd, Dd, Dd >> 6, sb, tid, lane, wm, wn, acc);

    const int rr = lane >> 2;
    const int cc = 2 * (lane & 3);
    const int n_base = bx * TN_CTA + wn * 64;
    const int m_base = by * TM_CTA + wm * 64;

    if (is_sc) {
        __half* outp = Sh + (size_t)z * Sq * Sq;
        #pragma unroll
        for (int i = 0; i < 4; i++)
            #pragma unroll
            for (int j = 0; j < 8; j++) {
                const int col = n_base + j * 8 + cc;
                #pragma unroll
                for (int h = 0; h < 2; h++) {
                    const int row = m_base + i * 16 + rr + h * 8;
                    size_t o = (size_t)row * Sq + col;
                    *(__half2*)(outp + o) = __halves2half2(
                        __float2half_rn(acc[i][j][2 * h] * scale),
                        __float2half_rn(acc[i][j][2 * h + 1] * scale));
                }
            }
    } else {
        __half* outp = vwot + (size_t)z * Dd * Sq;
        #pragma unroll
        for (int i = 0; i < 4; i++)
            #pragma unroll
            for (int j = 0; j < 8; j++) {
                const int col = n_base + j * 8 + cc;
                #pragma unroll
                for (int h = 0; h < 2; h++) {
                    const int row = m_base + i * 16 + rr + h * 8;
                    size_t o = (size_t)row * Sq + col;
                    *(__half2*)(outp + o) = __halves2half2(
                        __float2half_rn(acc[i][j][2 * h]),
                        __float2half_rn(acc[i][j][2 * h + 1]));
                }
            }
    }
}

// ================= PV GEMM: out = P · (V·Wo)^T + bo (fp32) =================
__global__ __launch_bounds__(NTHR, 2)
void gemm_pv(const __half* __restrict__ ph, const __half* __restrict__ vwot,
             const float* __restrict__ bo, float* __restrict__ out)
{
    const int bx = blockIdx.x, z = blockIdx.z;
    const int by = (int)gridDim.y - 1 - (int)blockIdx.y;   // heavy tiles first
    const int nchunk = ((by + 1) * 128) >> 6;              // causal K bound

    extern __shared__ __align__(16) char smem[];
    const uint32_t sb = smem_u32(smem);
    const int tid  = threadIdx.x;
    const int lane = tid & 31;
    const int wid  = tid >> 5;
    const int wm   = wid >> 1;
    const int wn   = wid & 1;

    float acc[4][8][4] = {};
    mainloop(ph + (size_t)z * Sq * Sq + (size_t)by * TM_CTA * Sq,
             vwot + (size_t)z * Dd * Sq + (size_t)bx * TN_CTA * Sq,
             Sq, Sq, nchunk, sb, tid, lane, wm, wn, acc);

    const int m_base = by * TM_CTA + wm * 64;
    const int n_base = bx * TN_CTA + wn * 64;
    const int rr = lane >> 2;
    const int cc = 2 * (lane & 3);
    float* outp = out + (size_t)z * Sq * Dd;

    #pragma unroll
    for (int j = 0; j < 8; j++) {
        const int col = n_base + j * 8 + cc;
        const float b0 = __ldg(&bo[col]);
        const float b1 = __ldg(&bo[col + 1]);
        #pragma unroll
        for (int i = 0; i < 4; i++) {
            #pragma unroll
            for (int h = 0; h < 2; h++) {
                const int row = m_base + i * 16 + rr + h * 8;
                float2 o = make_float2(acc[i][j][2 * h] + b0,
                                       acc[i][j][2 * h + 1] + b1);
                *(float2*)(outp + (size_t)row * Dd + col) = o;
            }
        }
    }
}

// ---------------- launch ----------------
extern "C" void kernel_launch(void* const* d_in, const int* in_sizes, int n_in,
                              void* d_out, int out_size)
{
    const float* x  = (const float*)d_in[0];
    const float* Wq = (const float*)d_in[1];
    const float* bq = (const float*)d_in[2];
    const float* Wk = (const float*)d_in[3];
    const float* bk = (const float*)d_in[4];
    const float* Wv = (const float*)d_in[5];
    const float* bv = (const float*)d_in[6];
    const float* Wo = (const float*)d_in[7];
    const float* bo = (const float*)d_in[8];
    float* out = (float*)d_out;

    __half *xr, *wqt, *wkt, *wvt, *wot, *qh, *kh, *vh, *vwot, *phv, *Shp;
    cudaGetSymbolAddress((void**)&xr,   g_xr);
    cudaGetSymbolAddress((void**)&wqt,  g_wqt);  cudaGetSymbolAddress((void**)&wkt, g_wkt);
    cudaGetSymbolAddress((void**)&wvt,  g_wvt);  cudaGetSymbolAddress((void**)&wot, g_wot);
    cudaGetSymbolAddress((void**)&qh,   g_qh);
    cudaGetSymbolAddress((void**)&kh,   g_kh);
    cudaGetSymbolAddress((void**)&vh,   g_vh);
    cudaGetSymbolAddress((void**)&vwot, g_vwot);
    cudaGetSymbolAddress((void**)&phv,  g_ph);
    cudaGetSymbolAddress((void**)&Shp,  g_Sh);

    cudaFuncSetAttribute(gemm_qkv,  cudaFuncAttributeMaxDynamicSharedMemorySize, GEMM_SMEM);
    cudaFuncSetAttribute(gemm_scvw, cudaFuncAttributeMaxDynamicSharedMemorySize, GEMM_SMEM);
    cudaFuncSetAttribute(gemm_pv,   cudaFuncAttributeMaxDynamicSharedMemorySize, GEMM_SMEM);

    const float scale = 1.0f / 32.0f;

    // #1: prep — weight transposes (z<4) + x rounding (z==4)
    dim3 tb(32, 8), tgp(Dd / 32, Dd / 32, 5);
    prep_kernel<<<tgp, tb>>>(x, xr, Wq, wqt, Wk, wkt, Wv, wvt, Wo, wot);

    // #2: combined QKV projection
    dim3 gQKV(24, Mm / TM_CTA, 1);
    gemm_qkv<<<gQKV, NTHR, GEMM_SMEM>>>(xr, wqt, wkt, wvt, bq, bk, bv, qh, kh, vh);

    // #3: merged scores + VWo, compact triangular grid (no dead CTAs)
    dim3 gSV(136 + 128, 1, Bn);                   // 264 x 1 x 4
    gemm_scvw<<<gSV, NTHR, GEMM_SMEM>>>(qh, kh, wot, vh, Shp, vwot, scale);

    // #4 (ncu capture slot): one-load fp16 softmax
    softmax_causal<<<Mm, 256>>>(Shp, phv);

    // #5: out = P·(V·Wo)^T + bo, fp32, K causally bounded
    dim3 gPV(Dd / TN_CTA, Sq / TM_CTA, Bn);       // 8 x 16 x 4
    gemm_pv<<<gPV, NTHR, GEMM_SMEM>>>(phv, vwot, bo, out);
}

// round 16
// speedup vs baseline: 1.0124x; 1.0124x over previous
#include <cuda_runtime.h>
#include <cuda_fp16.h>
#include <cstdint>

// SingleSelfHeadAttention b=4, s=2048, d=1024, causal, fp32 I/O.
// R16: warp-per-row softmax (no barriers, shuffle-only), vectorized prep.
//      GEMMs at the SMEM-crossbar wall (68% tensor) unchanged.

static constexpr int Bn = 4;
static constexpr int Sq = 2048;
static constexpr int Dd = 1024;
static constexpr int Mm = Bn * Sq;          // 8192

// ---------------- device scratch ----------------
__device__ __half g_xr [(size_t)Mm * Dd];
__device__ __half g_wqt[(size_t)Dd * Dd], g_wkt[(size_t)Dd * Dd];
__device__ __half g_wvt[(size_t)Dd * Dd], g_wot[(size_t)Dd * Dd];
__device__ __half g_qh[(size_t)Mm * Dd];
__device__ __half g_kh[(size_t)Mm * Dd];
__device__ __half g_vh[(size_t)Mm * Dd];
__device__ __half g_vwot[(size_t)Bn * Dd * Sq];   // (V·Wo)^T per batch [d'][s]
__device__ __half g_Sh[(size_t)Bn * Sq * Sq];     // fp16 scores
__device__ __half g_ph[(size_t)Bn * Sq * Sq];     // fp16 probs

// ---------------- PTX helpers ----------------
__device__ __forceinline__ uint32_t smem_u32(const void* p) {
    uint32_t a;
    asm("{ .reg .u64 t; cvta.to.shared.u64 t, %1; cvt.u32.u64 %0, t; }" : "=r"(a) : "l"(p));
    return a;
}
#define CP_ASYNC16(dst, src) \
    asm volatile("cp.async.cg.shared.global [%0], [%1], 16;" :: "r"(dst), "l"(src))
#define CP_COMMIT() asm volatile("cp.async.commit_group;" ::: "memory")
#define CP_WAIT1()  asm volatile("cp.async.wait_group 1;" ::: "memory")

__device__ __forceinline__ void ldsm_x4(uint32_t* r, uint32_t addr) {
    asm volatile("ldmatrix.sync.aligned.m8n8.x4.shared.b16 {%0,%1,%2,%3}, [%4];"
        : "=r"(r[0]), "=r"(r[1]), "=r"(r[2]), "=r"(r[3]) : "r"(addr));
}
__device__ __forceinline__ void mma_f16(float* c, const uint32_t* a, const uint32_t* b) {
    asm volatile("mma.sync.aligned.m16n8k16.row.col.f32.f16.f16.f32 "
        "{%0,%1,%2,%3}, {%4,%5,%6,%7}, {%8,%9}, {%0,%1,%2,%3};"
        : "+f"(c[0]), "+f"(c[1]), "+f"(c[2]), "+f"(c[3])
        : "r"(a[0]), "r"(a[1]), "r"(a[2]), "r"(a[3]), "r"(b[0]), "r"(b[1]));
}
__device__ __forceinline__ uint32_t swz(uint32_t off) {   // 128B-row XOR swizzle
    return off ^ ((off >> 3) & 0x70);
}

// ---------------- GEMM config: 128x128 tile, 128 threads ----------------
#define TM_CTA 128
#define TN_CTA 128
#define NTHR   128
#define A_TILE (TM_CTA * 128)            // 16384 B
#define STAGE  (2 * A_TILE)              // 32768
#define NSTAGE 3
#define GEMM_SMEM (NSTAGE * STAGE)       // 98304 -> 2 CTAs/SM

__device__ __forceinline__ void load_T_async(uint32_t dst, const __half* src,
                                             int ldK, int tid) {
    #pragma unroll
    for (int j = 0; j < 8; j++) {
        int s = tid + j * NTHR;
        int r = s >> 3, c = s & 7;
        CP_ASYNC16(dst + swz(r * 128 + c * 16), src + (size_t)r * ldK + c * 8);
    }
}

// Shared single-barrier multistage mainloop. acc[4][8][4] += A·B^T over nchunk*64 K.
__device__ __forceinline__ void mainloop(const __half* __restrict__ pA,
                                         const __half* __restrict__ pB,
                                         int ldA, int ldB, int nchunk,
                                         uint32_t sb, int tid, int lane,
                                         int wm, int wn, float acc[4][8][4])
{
    #pragma unroll
    for (int p = 0; p < 2; p++) {
        if (p < nchunk) {
            uint32_t st = sb + p * STAGE;
            load_T_async(st, pA + ((size_t)p << 6), ldA, tid);
            load_T_async(st + A_TILE, pB + ((size_t)p << 6), ldB, tid);
        }
        CP_COMMIT();
    }

    const uint32_t arow = (lane & 7) + ((lane & 8)  ? 8 : 0);
    const uint32_t acol = (lane & 16) ? 16u : 0u;
    const uint32_t brow = (lane & 7) + ((lane & 16) ? 8 : 0);
    const uint32_t bcol = (lane & 8)  ? 16u : 0u;

    for (int c = 0; c < nchunk; ++c) {
        CP_WAIT1();
        __syncthreads();

        if (c + 2 < nchunk) {
            uint32_t st = sb + ((c + 2) % NSTAGE) * STAGE;
            load_T_async(st, pA + ((size_t)(c + 2) << 6), ldA, tid);
            load_T_async(st + A_TILE, pB + ((size_t)(c + 2) << 6), ldB, tid);
        }
        CP_COMMIT();

        const uint32_t base = sb + (c % NSTAGE) * STAGE;
        #pragma unroll
        for (int ks = 0; ks < 4; ks++) {
            const uint32_t kb = ks * 32;
            uint32_t ah[4][4];
            #pragma unroll
            for (int i = 0; i < 4; i++) {
                uint32_t off = swz((wm * 64 + i * 16 + arow) * 128 + kb + acol);
                ldsm_x4(ah[i], base + off);
            }
            #pragma unroll
            for (int j2 = 0; j2 < 4; j2++) {
                uint32_t off = swz((wn * 64 + j2 * 16 + brow) * 128 + kb + bcol);
                uint32_t th[4];
                ldsm_x4(th, base + A_TILE + off);
                const int j0 = j2 * 2, j1 = j2 * 2 + 1;
                #pragma unroll
                for (int i = 0; i < 4; i++) {
                    mma_f16(acc[i][j0], ah[i], &th[0]);
                    mma_f16(acc[i][j1], ah[i], &th[2]);
                }
            }
        }
    }
}

// ---------------- prep: weight transposes (z<4) + x rounding (z==4) --------
__global__ void prep_kernel(const float* __restrict__ x, __half* __restrict__ xr,
                            const float* __restrict__ W0, __half* __restrict__ T0,
                            const float* __restrict__ W1, __half* __restrict__ T1,
                            const float* __restrict__ W2, __half* __restrict__ T2,
                            const float* __restrict__ W3, __half* __restrict__ T3) {
    if (blockIdx.z == 4) {
        // vectorized float4 -> half2x2 rounding (8M elements, 2M float4)
        const float4* x4 = (const float4*)x;
        __half2* o2 = (__half2*)xr;
        size_t i = ((size_t)(blockIdx.y * gridDim.x + blockIdx.x) * 256
                   + threadIdx.y * 32 + threadIdx.x);
        size_t stride = (size_t)gridDim.x * gridDim.y * 256;
        const size_t n4 = (size_t)Mm * Dd / 4;
        for (; i < n4; i += stride) {
            float4 t = x4[i];
            o2[2 * i]     = __halves2half2(__float2half_rn(t.x), __float2half_rn(t.y));
            o2[2 * i + 1] = __halves2half2(__float2half_rn(t.z), __float2half_rn(t.w));
        }
        return;
    }
    const float* W = (blockIdx.z == 0) ? W0 : (blockIdx.z == 1) ? W1
                   : (blockIdx.z == 2) ? W2 : W3;
    __half* T = (blockIdx.z == 0) ? T0 : (blockIdx.z == 1) ? T1
              : (blockIdx.z == 2) ? T2 : T3;
    __shared__ float tile[32][33];
    int bx = blockIdx.x * 32, by = blockIdx.y * 32;
    int tx = threadIdx.x, ty = threadIdx.y;
    #pragma unroll
    for (int j = 0; j < 4; j++)
        tile[ty + 8 * j][tx] = W[(size_t)(by + ty + 8 * j) * Dd + bx + tx];
    __syncthreads();
    #pragma unroll
    for (int j = 0; j < 4; j++) {
        float v = tile[tx][ty + 8 * j];
        size_t o = (size_t)(bx + ty + 8 * j) * Dd + by + tx;
        T[o] = __float2half_rn(v);
    }
}

// Warp-per-row causal softmax: 8 warps/block, one full row per warp.
// Lane owns 8 uint4 (64 fp16). Shuffle-only reductions; no smem, no barriers.
__global__ __launch_bounds__(256)
void softmax_causal(const __half* __restrict__ Sh, __half* __restrict__ ph) {
    const int lane = threadIdx.x & 31;
    const int wrp  = threadIdx.x >> 5;
    const int gq   = blockIdx.x * 8 + wrp;
    const int q    = gq & (Sq - 1);
    const uint4* row = (const uint4*)(Sh + (size_t)gq * Sq);   // 256 uint4
    uint4* out = (uint4*)(ph + (size_t)gq * Sq);
    const int len   = q + 1;
    const int jend4 = ((q >> 7) + 1) << 4;        // pad bound in uint4 units

    float v[64];
    #pragma unroll
    for (int k = 0; k < 8; k++) {
        const int idx  = k * 32 + lane;
        const int col0 = idx << 3;
        if (col0 < len) {
            uint4 t = row[idx];
            const __half2* h2 = (const __half2*)&t;
            #pragma unroll
            for (int e = 0; e < 4; e++) {
                float2 f = __half22float2(h2[e]);
                v[k * 8 + 2 * e]     = (col0 + 2 * e     < len) ? f.x : -1e30f;
                v[k * 8 + 2 * e + 1] = (col0 + 2 * e + 1 < len) ? f.y : -1e30f;
            }
        } else {
            #pragma unroll
            for (int e = 0; e < 8; e++) v[k * 8 + e] = -1e30f;
        }
    }

    float m = -1e30f;
    #pragma unroll
    for (int e = 0; e < 64; e++) m = fmaxf(m, v[e]);
    #pragma unroll
    for (int o = 16; o > 0; o >>= 1)
        m = fmaxf(m, __shfl_xor_sync(0xffffffffu, m, o));

    float sum = 0.f;
    #pragma unroll
    for (int e = 0; e < 64; e++) {
        float x = __expf(v[e] - m);   // -1e30 -> 0: masks AND zero-pads
        v[e] = x; sum += x;
    }
    #pragma unroll
    for (int o = 16; o > 0; o >>= 1)
        sum += __shfl_xor_sync(0xffffffffu, sum, o);
    const float inv = 1.0f / sum;

    #pragma unroll
    for (int k = 0; k < 8; k++) {
        const int idx = k * 32 + lane;
        if (idx < jend4) {
            uint4 o4;
            __half2* h2 = (__half2*)&o4;
            #pragma unroll
            for (int e = 0; e < 4; e++)
                h2[e] = __halves2half2(
                    __float2half_rn(v[k * 8 + 2 * e] * inv),
                    __float2half_rn(v[k * 8 + 2 * e + 1] * inv));
            out[idx] = o4;
        }
    }
}

// ================= QKV combined single-pass GEMM =================
__global__ __launch_bounds__(NTHR, 2)
void gemm_qkv(const __half* __restrict__ xr,
              const __half* __restrict__ wq, const __half* __restrict__ wk,
              const __half* __restrict__ wv,
              const float* __restrict__ bq, const float* __restrict__ bk,
              const float* __restrict__ bv,
              __half* __restrict__ qh, __half* __restrict__ kh,
              __half* __restrict__ vh)
{
    const int bxx = blockIdx.x & 7;
    const int wsel = blockIdx.x >> 3;
    const int by = blockIdx.y;
    const __half* Bw  = (wsel == 0) ? wq : (wsel == 1) ? wk : wv;
    const float* bias = (wsel == 0) ? bq : (wsel == 1) ? bk : bv;
    __half* outp      = (wsel == 0) ? qh : (wsel == 1) ? kh : vh;

    extern __shared__ __align__(16) char smem[];
    const uint32_t sb = smem_u32(smem);
    const int tid  = threadIdx.x;
    const int lane = tid & 31;
    const int wid  = tid >> 5;
    const int wm   = wid >> 1;
    const int wn   = wid & 1;

    float acc[4][8][4] = {};
    mainloop(xr + (size_t)by * TM_CTA * Dd, Bw + (size_t)bxx * TN_CTA * Dd,
             Dd, Dd, Dd >> 6, sb, tid, lane, wm, wn, acc);

    const int m_base = by * TM_CTA + wm * 64;
    const int n_base = bxx * TN_CTA + wn * 64;
    const int rr = lane >> 2;
    const int cc = 2 * (lane & 3);

    #pragma unroll
    for (int j = 0; j < 8; j++) {
        const int col = n_base + j * 8 + cc;
        const float b0 = __ldg(&bias[col]);
        const float b1 = __ldg(&bias[col + 1]);
        #pragma unroll
        for (int i = 0; i < 4; i++) {
            #pragma unroll
            for (int h = 0; h < 2; h++) {
                const int row = m_base + i * 16 + rr + h * 8;
                float v0 = acc[i][j][2 * h + 0] + b0;
                float v1 = acc[i][j][2 * h + 1] + b1;
                size_t o = (size_t)row * Dd + col;
                *(__half2*)(outp + o) =
                    __halves2half2(__float2half_rn(v0), __float2half_rn(v1));
            }
        }
    }
}

// ================= merged scores + (V·Wo)^T GEMM, compact grid =================
// grid.x = 264: t<136 -> triangular score tile (by,bx); t>=136 -> vwo tile.
__global__ __launch_bounds__(NTHR, 2)
void gemm_scvw(const __half* __restrict__ qh, const __half* __restrict__ kh,
               const __half* __restrict__ wot, const __half* __restrict__ vh,
               __half* __restrict__ Sh, __half* __restrict__ vwot, float scale)
{
    const int t = blockIdx.x;
    const int z = blockIdx.z;
    const bool is_sc = (t < 136);
    int by, bx;
    if (is_sc) {
        by = (int)((sqrtf(8.f * t + 1.f) - 1.f) * 0.5f);
        while ((by + 1) * (by + 2) / 2 <= t) by++;
        while (by * (by + 1) / 2 > t) by--;
        bx = t - by * (by + 1) / 2;               // bx <= by (causal)
    } else {
        const int t2 = t - 136;                   // 0..127
        by = t2 >> 4;                             // 0..7  (wot row tile)
        bx = t2 & 15;                             // 0..15 (seq col tile)
    }

    extern __shared__ __align__(16) char smem[];
    const uint32_t sb = smem_u32(smem);
    const int tid  = threadIdx.x;
    const int lane = tid & 31;
    const int wid  = tid >> 5;
    const int wm   = wid >> 1;
    const int wn   = wid & 1;

    const __half* pA;
    const __half* pB;
    if (is_sc) {
        pA = qh + (size_t)z * Sq * Dd + (size_t)by * TM_CTA * Dd;
        pB = kh + (size_t)z * Sq * Dd + (size_t)bx * TN_CTA * Dd;
    } else {
        pA = wot + (size_t)by * TM_CTA * Dd;
        pB = vh + (size_t)z * Sq * Dd + (size_t)bx * TN_CTA * Dd;
    }

    float acc[4][8][4] = {};
    mainloop(pA, pB, Dd, Dd, Dd >> 6, sb, tid, lane, wm, wn, acc);

    const int rr = lane >> 2;
    const int cc = 2 * (lane & 3);
    const int n_base = bx * TN_CTA + wn * 64;
    const int m_base = by * TM_CTA + wm * 64;

    if (is_sc) {
        __half* outp = Sh + (size_t)z * Sq * Sq;
        #pragma unroll
        for (int i = 0; i < 4; i++)
            #pragma unroll
            for (int j = 0; j < 8; j++) {
                const int col = n_base + j * 8 + cc;
                #pragma unroll
                for (int h = 0; h < 2; h++) {
                    const int row = m_base + i * 16 + rr + h * 8;
                    size_t o = (size_t)row * Sq + col;
                    *(__half2*)(outp + o) = __halves2half2(
                        __float2half_rn(acc[i][j][2 * h] * scale),
                        __float2half_rn(acc[i][j][2 * h + 1] * scale));
                }
            }
    } else {
        __half* outp = vwot + (size_t)z * Dd * Sq;
        #pragma unroll
        for (int i = 0; i < 4; i++)
            #pragma unroll
            for (int j = 0; j < 8; j++) {
                const int col = n_base + j * 8 + cc;
                #pragma unroll
                for (int h = 0; h < 2; h++) {
                    const int row = m_base + i * 16 + rr + h * 8;
                    size_t o = (size_t)row * Sq + col;
                    *(__half2*)(outp + o) = __halves2half2(
                        __float2half_rn(acc[i][j][2 * h]),
                        __float2half_rn(acc[i][j][2 * h + 1]));
                }
            }
    }
}

// ================= PV GEMM: out = P · (V·Wo)^T + bo (fp32) =================
__global__ __launch_bounds__(NTHR, 2)
void gemm_pv(const __half* __restrict__ ph, const __half* __restrict__ vwot,
             const float* __restrict__ bo, float* __restrict__ out)
{
    const int bx = blockIdx.x, z = blockIdx.z;
    const int by = (int)gridDim.y - 1 - (int)blockIdx.y;   // heavy tiles first
    const int nchunk = ((by + 1) * 128) >> 6;              // causal K bound

    extern __shared__ __align__(16) char smem[];
    const uint32_t sb = smem_u32(smem);
    const int tid  = threadIdx.x;
    const int lane = tid & 31;
    const int wid  = tid >> 5;
    const int wm   = wid >> 1;
    const int wn   = wid & 1;

    float acc[4][8][4] = {};
    mainloop(ph + (size_t)z * Sq * Sq + (size_t)by * TM_CTA * Sq,
             vwot + (size_t)z * Dd * Sq + (size_t)bx * TN_CTA * Sq,
             Sq, Sq, nchunk, sb, tid, lane, wm, wn, acc);

    const int m_base = by * TM_CTA + wm * 64;
    const int n_base = bx * TN_CTA + wn * 64;
    const int rr = lane >> 2;
    const int cc = 2 * (lane & 3);
    float* outp = out + (size_t)z * Sq * Dd;

    #pragma unroll
    for (int j = 0; j < 8; j++) {
        const int col = n_base + j * 8 + cc;
        const float b0 = __ldg(&bo[col]);
        const float b1 = __ldg(&bo[col + 1]);
        #pragma unroll
        for (int i = 0; i < 4; i++) {
            #pragma unroll
            for (int h = 0; h < 2; h++) {
                const int row = m_base + i * 16 + rr + h * 8;
                float2 o = make_float2(acc[i][j][2 * h] + b0,
                                       acc[i][j][2 * h + 1] + b1);
                *(float2*)(outp + (size_t)row * Dd + col) = o;
            }
        }
    }
}

// ---------------- launch ----------------
extern "C" void kernel_launch(void* const* d_in, const int* in_sizes, int n_in,
                              void* d_out, int out_size)
{
    const float* x  = (const float*)d_in[0];
    const float* Wq = (const float*)d_in[1];
    const float* bq = (const float*)d_in[2];
    const float* Wk = (const float*)d_in[3];
    const float* bk = (const float*)d_in[4];
    const float* Wv = (const float*)d_in[5];
    const float* bv = (const float*)d_in[6];
    const float* Wo = (const float*)d_in[7];
    const float* bo = (const float*)d_in[8];
    float* out = (float*)d_out;

    __half *xr, *wqt, *wkt, *wvt, *wot, *qh, *kh, *vh, *vwot, *phv, *Shp;
    cudaGetSymbolAddress((void**)&xr,   g_xr);
    cudaGetSymbolAddress((void**)&wqt,  g_wqt);  cudaGetSymbolAddress((void**)&wkt, g_wkt);
    cudaGetSymbolAddress((void**)&wvt,  g_wvt);  cudaGetSymbolAddress((void**)&wot, g_wot);
    cudaGetSymbolAddress((void**)&qh,   g_qh);
    cudaGetSymbolAddress((void**)&kh,   g_kh);
    cudaGetSymbolAddress((void**)&vh,   g_vh);
    cudaGetSymbolAddress((void**)&vwot, g_vwot);
    cudaGetSymbolAddress((void**)&phv,  g_ph);
    cudaGetSymbolAddress((void**)&Shp,  g_Sh);

    cudaFuncSetAttribute(gemm_qkv,  cudaFuncAttributeMaxDynamicSharedMemorySize, GEMM_SMEM);
    cudaFuncSetAttribute(gemm_scvw, cudaFuncAttributeMaxDynamicSharedMemorySize, GEMM_SMEM);
    cudaFuncSetAttribute(gemm_pv,   cudaFuncAttributeMaxDynamicSharedMemorySize, GEMM_SMEM);

    const float scale = 1.0f / 32.0f;

    // #1: prep — weight transposes (z<4) + vectorized x rounding (z==4)
    dim3 tb(32, 8), tgp(Dd / 32, Dd / 32, 5);
    prep_kernel<<<tgp, tb>>>(x, xr, Wq, wqt, Wk, wkt, Wv, wvt, Wo, wot);

    // #2: combined QKV projection
    dim3 gQKV(24, Mm / TM_CTA, 1);
    gemm_qkv<<<gQKV, NTHR, GEMM_SMEM>>>(xr, wqt, wkt, wvt, bq, bk, bv, qh, kh, vh);

    // #3: merged scores + VWo, compact triangular grid
    dim3 gSV(136 + 128, 1, Bn);                   // 264 x 1 x 4
    gemm_scvw<<<gSV, NTHR, GEMM_SMEM>>>(qh, kh, wot, vh, Shp, vwot, scale);

    // #4 (ncu capture slot): warp-per-row softmax
    softmax_causal<<<Mm / 8, 256>>>(Shp, phv);

    // #5: out = P·(V·Wo)^T + bo, fp32, K causally bounded
    dim3 gPV(Dd / TN_CTA, Sq / TM_CTA, Bn);       // 8 x 16 x 4
    gemm_pv<<<gPV, NTHR, GEMM_SMEM>>>(phv, vwot, bo, out);
}

// round 17
// speedup vs baseline: 1.0167x; 1.0043x over previous
#include <cuda_runtime.h>
#include <cuda_fp16.h>
#include <cstdint>

// SingleSelfHeadAttention b=4, s=2048, d=1024, causal, fp32 I/O.
// R17: packed-fp16-register softmax (hmax2, dynamic granule bound, exp
//      recompute) to fix occupancy. GEMMs at the crossbar wall unchanged.

static constexpr int Bn = 4;
static constexpr int Sq = 2048;
static constexpr int Dd = 1024;
static constexpr int Mm = Bn * Sq;          // 8192

// ---------------- device scratch ----------------
__device__ __half g_xr [(size_t)Mm * Dd];
__device__ __half g_wqt[(size_t)Dd * Dd], g_wkt[(size_t)Dd * Dd];
__device__ __half g_wvt[(size_t)Dd * Dd], g_wot[(size_t)Dd * Dd];
__device__ __half g_qh[(size_t)Mm * Dd];
__device__ __half g_kh[(size_t)Mm * Dd];
__device__ __half g_vh[(size_t)Mm * Dd];
__device__ __half g_vwot[(size_t)Bn * Dd * Sq];   // (V·Wo)^T per batch [d'][s]
__device__ __half g_Sh[(size_t)Bn * Sq * Sq];     // fp16 scores
__device__ __half g_ph[(size_t)Bn * Sq * Sq];     // fp16 probs

// ---------------- PTX helpers ----------------
__device__ __forceinline__ uint32_t smem_u32(const void* p) {
    uint32_t a;
    asm("{ .reg .u64 t; cvta.to.shared.u64 t, %1; cvt.u32.u64 %0, t; }" : "=r"(a) : "l"(p));
    return a;
}
#define CP_ASYNC16(dst, src) \
    asm volatile("cp.async.cg.shared.global [%0], [%1], 16;" :: "r"(dst), "l"(src))
#define CP_COMMIT() asm volatile("cp.async.commit_group;" ::: "memory")
#define CP_WAIT1()  asm volatile("cp.async.wait_group 1;" ::: "memory")

__device__ __forceinline__ void ldsm_x4(uint32_t* r, uint32_t addr) {
    asm volatile("ldmatrix.sync.aligned.m8n8.x4.shared.b16 {%0,%1,%2,%3}, [%4];"
        : "=r"(r[0]), "=r"(r[1]), "=r"(r[2]), "=r"(r[3]) : "r"(addr));
}
__device__ __forceinline__ void mma_f16(float* c, const uint32_t* a, const uint32_t* b) {
    asm volatile("mma.sync.aligned.m16n8k16.row.col.f32.f16.f16.f32 "
        "{%0,%1,%2,%3}, {%4,%5,%6,%7}, {%8,%9}, {%0,%1,%2,%3};"
        : "+f"(c[0]), "+f"(c[1]), "+f"(c[2]), "+f"(c[3])
        : "r"(a[0]), "r"(a[1]), "r"(a[2]), "r"(a[3]), "r"(b[0]), "r"(b[1]));
}
__device__ __forceinline__ uint32_t swz(uint32_t off) {   // 128B-row XOR swizzle
    return off ^ ((off >> 3) & 0x70);
}

// ---------------- GEMM config: 128x128 tile, 128 threads ----------------
#define TM_CTA 128
#define TN_CTA 128
#define NTHR   128
#define A_TILE (TM_CTA * 128)            // 16384 B
#define STAGE  (2 * A_TILE)              // 32768
#define NSTAGE 3
#define GEMM_SMEM (NSTAGE * STAGE)       // 98304 -> 2 CTAs/SM

__device__ __forceinline__ void load_T_async(uint32_t dst, const __half* src,
                                             int ldK, int tid) {
    #pragma unroll
    for (int j = 0; j < 8; j++) {
        int s = tid + j * NTHR;
        int r = s >> 3, c = s & 7;
        CP_ASYNC16(dst + swz(r * 128 + c * 16), src + (size_t)r * ldK + c * 8);
    }
}

// Shared single-barrier multistage mainloop. acc[4][8][4] += A·B^T over nchunk*64 K.
__device__ __forceinline__ void mainloop(const __half* __restrict__ pA,
                                         const __half* __restrict__ pB,
                                         int ldA, int ldB, int nchunk,
                                         uint32_t sb, int tid, int lane,
                                         int wm, int wn, float acc[4][8][4])
{
    #pragma unroll
    for (int p = 0; p < 2; p++) {
        if (p < nchunk) {
            uint32_t st = sb + p * STAGE;
            load_T_async(st, pA + ((size_t)p << 6), ldA, tid);
            load_T_async(st + A_TILE, pB + ((size_t)p << 6), ldB, tid);
        }
        CP_COMMIT();
    }

    const uint32_t arow = (lane & 7) + ((lane & 8)  ? 8 : 0);
    const uint32_t acol = (lane & 16) ? 16u : 0u;
    const uint32_t brow = (lane & 7) + ((lane & 16) ? 8 : 0);
    const uint32_t bcol = (lane & 8)  ? 16u : 0u;

    for (int c = 0; c < nchunk; ++c) {
        CP_WAIT1();
        __syncthreads();

        if (c + 2 < nchunk) {
            uint32_t st = sb + ((c + 2) % NSTAGE) * STAGE;
            load_T_async(st, pA + ((size_t)(c + 2) << 6), ldA, tid);
            load_T_async(st + A_TILE, pB + ((size_t)(c + 2) << 6), ldB, tid);
        }
        CP_COMMIT();

        const uint32_t base = sb + (c % NSTAGE) * STAGE;
        #pragma unroll
        for (int ks = 0; ks < 4; ks++) {
            const uint32_t kb = ks * 32;
            uint32_t ah[4][4];
            #pragma unroll
            for (int i = 0; i < 4; i++) {
                uint32_t off = swz((wm * 64 + i * 16 + arow) * 128 + kb + acol);
                ldsm_x4(ah[i], base + off);
            }
            #pragma unroll
            for (int j2 = 0; j2 < 4; j2++) {
                uint32_t off = swz((wn * 64 + j2 * 16 + brow) * 128 + kb + bcol);
                uint32_t th[4];
                ldsm_x4(th, base + A_TILE + off);
                const int j0 = j2 * 2, j1 = j2 * 2 + 1;
                #pragma unroll
                for (int i = 0; i < 4; i++) {
                    mma_f16(acc[i][j0], ah[i], &th[0]);
                    mma_f16(acc[i][j1], ah[i], &th[2]);
                }
            }
        }
    }
}

// ---------------- prep: weight transposes (z<4) + x rounding (z==4) --------
__global__ void prep_kernel(const float* __restrict__ x, __half* __restrict__ xr,
                            const float* __restrict__ W0, __half* __restrict__ T0,
                            const float* __restrict__ W1, __half* __restrict__ T1,
                            const float* __restrict__ W2, __half* __restrict__ T2,
                            const float* __restrict__ W3, __half* __restrict__ T3) {
    if (blockIdx.z == 4) {
        const float4* x4 = (const float4*)x;
        __half2* o2 = (__half2*)xr;
        size_t i = ((size_t)(blockIdx.y * gridDim.x + blockIdx.x) * 256
                   + threadIdx.y * 32 + threadIdx.x);
        size_t stride = (size_t)gridDim.x * gridDim.y * 256;
        const size_t n4 = (size_t)Mm * Dd / 4;
        for (; i < n4; i += stride) {
            float4 t = x4[i];
            o2[2 * i]     = __halves2half2(__float2half_rn(t.x), __float2half_rn(t.y));
            o2[2 * i + 1] = __halves2half2(__float2half_rn(t.z), __float2half_rn(t.w));
        }
        return;
    }
    const float* W = (blockIdx.z == 0) ? W0 : (blockIdx.z == 1) ? W1
                   : (blockIdx.z == 2) ? W2 : W3;
    __half* T = (blockIdx.z == 0) ? T0 : (blockIdx.z == 1) ? T1
              : (blockIdx.z == 2) ? T2 : T3;
    __shared__ float tile[32][33];
    int bx = blockIdx.x * 32, by = blockIdx.y * 32;
    int tx = threadIdx.x, ty = threadIdx.y;
    #pragma unroll
    for (int j = 0; j < 4; j++)
        tile[ty + 8 * j][tx] = W[(size_t)(by + ty + 8 * j) * Dd + bx + tx];
    __syncthreads();
    #pragma unroll
    for (int j = 0; j < 4; j++) {
        float v = tile[tx][ty + 8 * j];
        size_t o = (size_t)(bx + ty + 8 * j) * Dd + by + tx;
        T[o] = __float2half_rn(v);
    }
}

// Warp-per-row causal softmax, packed-fp16 registers.
// Lane holds 8 uint4 (64 fp16). hmax2 max sweep, exp recompute on output.
__global__ __launch_bounds__(256)
void softmax_causal(const __half* __restrict__ Sh, __half* __restrict__ ph) {
    const int lane = threadIdx.x & 31;
    const int wrp  = threadIdx.x >> 5;
    const int gq   = blockIdx.x * 8 + wrp;
    const int q    = gq & (Sq - 1);
    const uint4* row = (const uint4*)(Sh + (size_t)gq * Sq);   // 256 uint4
    uint4* out = (uint4*)(ph + (size_t)gq * Sq);
    const int len   = q + 1;
    const int nact  = (len + 7) >> 3;             // active uint4 granules
    const int kmax  = (len + 255) >> 8;           // active k-groups (warp-wide)
    const int jend4 = ((q >> 7) + 1) << 4;        // pad bound in uint4 units

    const uint32_t NEGINF2 = 0xFC00FC00u;         // fp16 -inf pair
    uint4 t[8];

    #pragma unroll
    for (int k = 0; k < 8; k++) {
        if (k >= kmax) continue;
        const int idx  = k * 32 + lane;
        const int col0 = idx << 3;
        if (idx < nact) {
            t[k] = row[idx];
            if (col0 + 8 > len) {                 // partial granule: mask tail
                uint32_t* w = (uint32_t*)&t[k];
                #pragma unroll
                for (int e = 0; e < 4; e++) {
                    const int c2 = col0 + 2 * e;
                    if (c2 >= len) w[e] = NEGINF2;
                    else if (c2 + 1 >= len) w[e] = (w[e] & 0x0000FFFFu) | 0xFC000000u;
                }
            }
        } else {
            t[k].x = t[k].y = t[k].z = t[k].w = NEGINF2;
        }
    }

    // max sweep on packed halves
    __half2 hm = *(const __half2*)&NEGINF2;
    #pragma unroll
    for (int k = 0; k < 8; k++) {
        if (k >= kmax) continue;
        const __half2* h2 = (const __half2*)&t[k];
        #pragma unroll
        for (int e = 0; e < 4; e++) hm = __hmax2(hm, h2[e]);
    }
    float m = fmaxf(__low2float(hm), __high2float(hm));
    #pragma unroll
    for (int o = 16; o > 0; o >>= 1)
        m = fmaxf(m, __shfl_xor_sync(0xffffffffu, m, o));

    // sum sweep (exp discarded)
    float sum = 0.f;
    #pragma unroll
    for (int k = 0; k < 8; k++) {
        if (k >= kmax) continue;
        const __half2* h2 = (const __half2*)&t[k];
        #pragma unroll
        for (int e = 0; e < 4; e++) {
            float2 f = __half22float2(h2[e]);
            sum += __expf(f.x - m) + __expf(f.y - m);   // -inf -> 0
        }
    }
    #pragma unroll
    for (int o = 16; o > 0; o >>= 1)
        sum += __shfl_xor_sync(0xffffffffu, sum, o);
    const float inv = 1.0f / sum;

    // output sweep: recompute exp, scale, pack; zero the pad region
    #pragma unroll
    for (int k = 0; k < 8; k++) {
        const int idx = k * 32 + lane;
        if (idx >= jend4) continue;
        uint4 o4;
        if (k < kmax && idx < nact) {
            const __half2* h2 = (const __half2*)&t[k];
            __half2* g2 = (__half2*)&o4;
            #pragma unroll
            for (int e = 0; e < 4; e++) {
                float2 f = __half22float2(h2[e]);
                g2[e] = __halves2half2(
                    __float2half_rn(__expf(f.x - m) * inv),
                    __float2half_rn(__expf(f.y - m) * inv));
            }
        } else {
            o4.x = o4.y = o4.z = o4.w = 0u;
        }
        out[idx] = o4;
    }
}

// ================= QKV combined single-pass GEMM =================
__global__ __launch_bounds__(NTHR, 2)
void gemm_qkv(const __half* __restrict__ xr,
              const __half* __restrict__ wq, const __half* __restrict__ wk,
              const __half* __restrict__ wv,
              const float* __restrict__ bq, const float* __restrict__ bk,
              const float* __restrict__ bv,
              __half* __restrict__ qh, __half* __restrict__ kh,
              __half* __restrict__ vh)
{
    const int bxx = blockIdx.x & 7;
    const int wsel = blockIdx.x >> 3;
    const int by = blockIdx.y;
    const __half* Bw  = (wsel == 0) ? wq : (wsel == 1) ? wk : wv;
    const float* bias = (wsel == 0) ? bq : (wsel == 1) ? bk : bv;
    __half* outp      = (wsel == 0) ? qh : (wsel == 1) ? kh : vh;

    extern __shared__ __align__(16) char smem[];
    const uint32_t sb = smem_u32(smem);
    const int tid  = threadIdx.x;
    const int lane = tid & 31;
    const int wid  = tid >> 5;
    const int wm   = wid >> 1;
    const int wn   = wid & 1;

    float acc[4][8][4] = {};
    mainloop(xr + (size_t)by * TM_CTA * Dd, Bw + (size_t)bxx * TN_CTA * Dd,
             Dd, Dd, Dd >> 6, sb, tid, lane, wm, wn, acc);

    const int m_base = by * TM_CTA + wm * 64;
    const int n_base = bxx * TN_CTA + wn * 64;
    const int rr = lane >> 2;
    const int cc = 2 * (lane & 3);

    #pragma unroll
    for (int j = 0; j < 8; j++) {
        const int col = n_base + j * 8 + cc;
        const float b0 = __ldg(&bias[col]);
        const float b1 = __ldg(&bias[col + 1]);
        #pragma unroll
        for (int i = 0; i < 4; i++) {
            #pragma unroll
            for (int h = 0; h < 2; h++) {
                const int row = m_base + i * 16 + rr + h * 8;
                float v0 = acc[i][j][2 * h + 0] + b0;
                float v1 = acc[i][j][2 * h + 1] + b1;
                size_t o = (size_t)row * Dd + col;
                *(__half2*)(outp + o) =
                    __halves2half2(__float2half_rn(v0), __float2half_rn(v1));
            }
        }
    }
}

// ================= merged scores + (V·Wo)^T GEMM, compact grid =================
// grid.x = 264: t<136 -> triangular score tile (by,bx); t>=136 -> vwo tile.
__global__ __launch_bounds__(NTHR, 2)
void gemm_scvw(const __half* __restrict__ qh, const __half* __restrict__ kh,
               const __half* __restrict__ wot, const __half* __restrict__ vh,
               __half* __restrict__ Sh, __half* __restrict__ vwot, float scale)
{
    const int t = blockIdx.x;
    const int z = blockIdx.z;
    const bool is_sc = (t < 136);
    int by, bx;
    if (is_sc) {
        by = (int)((sqrtf(8.f * t + 1.f) - 1.f) * 0.5f);
        while ((by + 1) * (by + 2) / 2 <= t) by++;
        while (by * (by + 1) / 2 > t) by--;
        bx = t - by * (by + 1) / 2;               // bx <= by (causal)
    } else {
        const int t2 = t - 136;                   // 0..127
        by = t2 >> 4;                             // 0..7  (wot row tile)
        bx = t2 & 15;                             // 0..15 (seq col tile)
    }

    extern __shared__ __align__(16) char smem[];
    const uint32_t sb = smem_u32(smem);
    const int tid  = threadIdx.x;
    const int lane = tid & 31;
    const int wid  = tid >> 5;
    const int wm   = wid >> 1;
    const int wn   = wid & 1;

    const __half* pA;
    const __half* pB;
    if (is_sc) {
        pA = qh + (size_t)z * Sq * Dd + (size_t)by * TM_CTA * Dd;
        pB = kh + (size_t)z * Sq * Dd + (size_t)bx * TN_CTA * Dd;
    } else {
        pA = wot + (size_t)by * TM_CTA * Dd;
        pB = vh + (size_t)z * Sq * Dd + (size_t)bx * TN_CTA * Dd;
    }

    float acc[4][8][4] = {};
    mainloop(pA, pB, Dd, Dd, Dd >> 6, sb, tid, lane, wm, wn, acc);

    const int rr = lane >> 2;
    const int cc = 2 * (lane & 3);
    const int n_base = bx * TN_CTA + wn * 64;
    const int m_base = by * TM_CTA + wm * 64;

    if (is_sc) {
        __half* outp = Sh + (size_t)z * Sq * Sq;
        #pragma unroll
        for (int i = 0; i < 4; i++)
            #pragma unroll
            for (int j = 0; j < 8; j++) {
                const int col = n_base + j * 8 + cc;
                #pragma unroll
                for (int h = 0; h < 2; h++) {
                    const int row = m_base + i * 16 + rr + h * 8;
                    size_t o = (size_t)row * Sq + col;
                    *(__half2*)(outp + o) = __halves2half2(
                        __float2half_rn(acc[i][j][2 * h] * scale),
                        __float2half_rn(acc[i][j][2 * h + 1] * scale));
                }
            }
    } else {
        __half* outp = vwot + (size_t)z * Dd * Sq;
        #pragma unroll
        for (int i = 0; i < 4; i++)
            #pragma unroll
            for (int j = 0; j < 8; j++) {
                const int col = n_base + j * 8 + cc;
                #pragma unroll
                for (int h = 0; h < 2; h++) {
                    const int row = m_base + i * 16 + rr + h * 8;
                    size_t o = (size_t)row * Sq + col;
                    *(__half2*)(outp + o) = __halves2half2(
                        __float2half_rn(acc[i][j][2 * h]),
                        __float2half_rn(acc[i][j][2 * h + 1]));
                }
            }
    }
}

// ================= PV GEMM: out = P · (V·Wo)^T + bo (fp32) =================
__global__ __launch_bounds__(NTHR, 2)
void gemm_pv(const __half* __restrict__ ph, const __half* __restrict__ vwot,
             const float* __restrict__ bo, float* __restrict__ out)
{
    const int bx = blockIdx.x, z = blockIdx.z;
    const int by = (int)gridDim.y - 1 - (int)blockIdx.y;   // heavy tiles first
    const int nchunk = ((by + 1) * 128) >> 6;              // causal K bound

    extern __shared__ __align__(16) char smem[];
    const uint32_t sb = smem_u32(smem);
    const int tid  = threadIdx.x;
    const int lane = tid & 31;
    const int wid  = tid >> 5;
    const int wm   = wid >> 1;
    const int wn   = wid & 1;

    float acc[4][8][4] = {};
    mainloop(ph + (size_t)z * Sq * Sq + (size_t)by * TM_CTA * Sq,
             vwot + (size_t)z * Dd * Sq + (size_t)bx * TN_CTA * Sq,
             Sq, Sq, nchunk, sb, tid, lane, wm, wn, acc);

    const int m_base = by * TM_CTA + wm * 64;
    const int n_base = bx * TN_CTA + wn * 64;
    const int rr = lane >> 2;
    const int cc = 2 * (lane & 3);
    float* outp = out + (size_t)z * Sq * Dd;

    #pragma unroll
    for (int j = 0; j < 8; j++) {
        const int col = n_base + j * 8 + cc;
        const float b0 = __ldg(&bo[col]);
        const float b1 = __ldg(&bo[col + 1]);
        #pragma unroll
        for (int i = 0; i < 4; i++) {
            #pragma unroll
            for (int h = 0; h < 2; h++) {
                const int row = m_base + i * 16 + rr + h * 8;
                float2 o = make_float2(acc[i][j][2 * h] + b0,
                                       acc[i][j][2 * h + 1] + b1);
                *(float2*)(outp + (size_t)row * Dd + col) = o;
            }
        }
    }
}

// ---------------- launch ----------------
extern "C" void kernel_launch(void* const* d_in, const int* in_sizes, int n_in,
                              void* d_out, int out_size)
{
    const float* x  = (const float*)d_in[0];
    const float* Wq = (const float*)d_in[1];
    const float* bq = (const float*)d_in[2];
    const float* Wk = (const float*)d_in[3];
    const float* bk = (const float*)d_in[4];
    const float* Wv = (const float*)d_in[5];
    const float* bv = (const float*)d_in[6];
    const float* Wo = (const float*)d_in[7];
    const float* bo = (const float*)d_in[8];
    float* out = (float*)d_out;

    __half *xr, *wqt, *wkt, *wvt, *wot, *qh, *kh, *vh, *vwot, *phv, *Shp;
    cudaGetSymbolAddress((void**)&xr,   g_xr);
    cudaGetSymbolAddress((void**)&wqt,  g_wqt);  cudaGetSymbolAddress((void**)&wkt, g_wkt);
    cudaGetSymbolAddress((void**)&wvt,  g_wvt);  cudaGetSymbolAddress((void**)&wot, g_wot);
    cudaGetSymbolAddress((void**)&qh,   g_qh);
    cudaGetSymbolAddress((void**)&kh,   g_kh);
    cudaGetSymbolAddress((void**)&vh,   g_vh);
    cudaGetSymbolAddress((void**)&vwot, g_vwot);
    cudaGetSymbolAddress((void**)&phv,  g_ph);
    cudaGetSymbolAddress((void**)&Shp,  g_Sh);

    cudaFuncSetAttribute(gemm_qkv,  cudaFuncAttributeMaxDynamicSharedMemorySize, GEMM_SMEM);
    cudaFuncSetAttribute(gemm_scvw, cudaFuncAttributeMaxDynamicSharedMemorySize, GEMM_SMEM);
    cudaFuncSetAttribute(gemm_pv,   cudaFuncAttributeMaxDynamicSharedMemorySize, GEMM_SMEM);

    const float scale = 1.0f / 32.0f;

    // #1: prep — weight transposes (z<4) + vectorized x rounding (z==4)
    dim3 tb(32, 8), tgp(Dd / 32, Dd / 32, 5);
    prep_kernel<<<tgp, tb>>>(x, xr, Wq, wqt, Wk, wkt, Wv, wvt, Wo, wot);

    // #2: combined QKV projection
    dim3 gQKV(24, Mm / TM_CTA, 1);
    gemm_qkv<<<gQKV, NTHR, GEMM_SMEM>>>(xr, wqt, wkt, wvt, bq, bk, bv, qh, kh, vh);

    // #3: merged scores + VWo, compact triangular grid
    dim3 gSV(136 + 128, 1, Bn);                   // 264 x 1 x 4
    gemm_scvw<<<gSV, NTHR, GEMM_SMEM>>>(qh, kh, wot, vh, Shp, vwot, scale);

    // #4 (ncu capture slot): packed-register softmax
    softmax_causal<<<Mm / 8, 256>>>(Shp, phv);

    // #5: out = P·(V·Wo)^T + bo, fp32, K causally bounded
    dim3 gPV(Dd / TN_CTA, Sq / TM_CTA, Bn);       // 8 x 16 x 4
    gemm_pv<<<gPV, NTHR, GEMM_SMEM>>>(phv, vwot, bo, out);
}